// round 1
// baseline (speedup 1.0000x reference)
#include <cuda_runtime.h>
#include <math.h>

#define BS 4096
#define AGENTS 128
#define OBSD 128
#define ACT 8
#define SD 4096
#define EMB 32
#define H1 128
#define H2 64

// ---------------- scratch (static device globals; no allocation) ----------------
__device__ float g_qs[(size_t)BS * AGENTS];          // agent_qs [b][a]
__device__ float g_C[(size_t)BS * SD];               // qs-folded |w1| scratch [b][a*32+e]  (64MB)
__device__ float g_sb[(size_t)BS * EMB];             // states@Whb + bhb
__device__ float g_wf[(size_t)BS * EMB];             // |states@Whf + bhf|
__device__ float g_rv[(size_t)BS * EMB];             // relu(states@Wv1 + bv1)
__device__ float g_act_fallback[(size_t)BS * AGENTS];

// =============================================================================
// Kernel 1: fused per-agent 3-layer MLP + max/argmax.
// Grid (AGENTS, BS/64), 256 threads. Weights for agent a staged in smem once,
// 64 batch rows streamed. x1/x2 stay in smem; q stays in registers.
// =============================================================================
#define MLP_BT 64
#define MLP_SMEM ((64*132 + 64*68 + 64*132 + 128*128) * 4)

__global__ void __launch_bounds__(256) mlp_kernel(
    const float* __restrict__ obs,
    const float* __restrict__ W1, const float* __restrict__ b1,
    const float* __restrict__ W2, const float* __restrict__ b2,
    const float* __restrict__ W3, const float* __restrict__ b3,
    float* __restrict__ actions_out)
{
    extern __shared__ float sm[];
    float* x1s  = sm;                       // [64][132]
    float* x2s  = sm + 64*132;              // [64][68]
    float* obss = sm + 64*132 + 64*68;      // [64][132]
    float* ws   = sm + 64*132 + 64*68 + 64*132;  // up to [128][128]
    __shared__ float b1s[H1];
    __shared__ float b2s[H2];
    __shared__ float b3s[ACT];

    const int a   = blockIdx.x;
    const int b0  = blockIdx.y * MLP_BT;
    const int tid = threadIdx.x;

    if (tid < H1) b1s[tid] = b1[a*H1 + tid];
    if (tid < H2) b2s[tid] = b2[a*H2 + tid];
    if (tid < ACT) b3s[tid] = b3[a*ACT + tid];

    // stage W1 [128][128]
    {
        const float4* w1g = (const float4*)(W1 + (size_t)a * OBSD * H1);
        float4* wd = (float4*)ws;
        for (int i = tid; i < OBSD*H1/4; i += 256) wd[i] = w1g[i];
    }
    // stage obs tile (rows b0..b0+63 of agent a), padded stride 132
    for (int i = tid; i < MLP_BT * (OBSD/4); i += 256) {
        int r  = i >> 5;           // OBSD/4 = 32 float4 per row
        int c4 = i & 31;
        float4 v = ((const float4*)(obs + ((size_t)(b0 + r) * AGENTS + a) * OBSD))[c4];
        *(float4*)(obss + r*132 + c4*4) = v;
    }
    __syncthreads();

    // ---- layer 1: x1[64][128] = relu(obs @ W1 + b1) ----
    {
        const int ty = tid >> 4, tx = tid & 15;    // 16x16, rows ty*4.., cols tx*8..
        float acc[4][8];
        #pragma unroll
        for (int i = 0; i < 4; i++)
            #pragma unroll
            for (int j = 0; j < 8; j++) acc[i][j] = 0.f;

        #pragma unroll 4
        for (int k = 0; k < OBSD; k++) {
            float a0 = obss[(ty*4+0)*132 + k];
            float a1 = obss[(ty*4+1)*132 + k];
            float a2 = obss[(ty*4+2)*132 + k];
            float a3 = obss[(ty*4+3)*132 + k];
            float4 w0  = *(const float4*)(ws + k*H1 + tx*8);
            float4 w1v = *(const float4*)(ws + k*H1 + tx*8 + 4);
            float wv[8] = {w0.x,w0.y,w0.z,w0.w,w1v.x,w1v.y,w1v.z,w1v.w};
            #pragma unroll
            for (int j = 0; j < 8; j++) {
                acc[0][j] = fmaf(a0, wv[j], acc[0][j]);
                acc[1][j] = fmaf(a1, wv[j], acc[1][j]);
                acc[2][j] = fmaf(a2, wv[j], acc[2][j]);
                acc[3][j] = fmaf(a3, wv[j], acc[3][j]);
            }
        }
        #pragma unroll
        for (int i = 0; i < 4; i++)
            #pragma unroll
            for (int j = 0; j < 8; j++) {
                float v = acc[i][j] + b1s[tx*8 + j];
                x1s[(ty*4+i)*132 + tx*8 + j] = v > 0.f ? v : 0.f;
            }
    }
    __syncthreads();

    // stage W2 [128][64] (reuse ws)
    {
        const float4* w2g = (const float4*)(W2 + (size_t)a * H1 * H2);
        float4* wd = (float4*)ws;
        for (int i = tid; i < H1*H2/4; i += 256) wd[i] = w2g[i];
    }
    __syncthreads();

    // ---- layer 2: x2[64][64] = relu(x1 @ W2 + b2) ----
    {
        const int ty = tid >> 4, tx = tid & 15;    // rows ty*4.., cols tx*4..
        float acc[4][4];
        #pragma unroll
        for (int i = 0; i < 4; i++)
            #pragma unroll
            for (int j = 0; j < 4; j++) acc[i][j] = 0.f;

        #pragma unroll 4
        for (int k = 0; k < H1; k++) {
            float a0 = x1s[(ty*4+0)*132 + k];
            float a1 = x1s[(ty*4+1)*132 + k];
            float a2 = x1s[(ty*4+2)*132 + k];
            float a3 = x1s[(ty*4+3)*132 + k];
            float4 w = *(const float4*)(ws + k*H2 + tx*4);
            float wv[4] = {w.x, w.y, w.z, w.w};
            #pragma unroll
            for (int j = 0; j < 4; j++) {
                acc[0][j] = fmaf(a0, wv[j], acc[0][j]);
                acc[1][j] = fmaf(a1, wv[j], acc[1][j]);
                acc[2][j] = fmaf(a2, wv[j], acc[2][j]);
                acc[3][j] = fmaf(a3, wv[j], acc[3][j]);
            }
        }
        #pragma unroll
        for (int i = 0; i < 4; i++)
            #pragma unroll
            for (int j = 0; j < 4; j++) {
                float v = acc[i][j] + b2s[tx*4 + j];
                x2s[(ty*4+i)*68 + tx*4 + j] = v > 0.f ? v : 0.f;
            }
    }
    __syncthreads();

    // stage W3 [64][8]
    {
        const float4* w3g = (const float4*)(W3 + (size_t)a * H2 * ACT);
        float4* wd = (float4*)ws;
        for (int i = tid; i < H2*ACT/4; i += 256) wd[i] = w3g[i];
    }
    __syncthreads();

    // ---- layer 3 + max/argmax: one thread per batch row ----
    if (tid < MLP_BT) {
        const int r = tid;
        float acc[8];
        #pragma unroll
        for (int c = 0; c < 8; c++) acc[c] = 0.f;
        #pragma unroll 4
        for (int k = 0; k < H2; k++) {
            float x = x2s[r*68 + k];
            float4 w0  = *(const float4*)(ws + k*ACT);
            float4 w1v = *(const float4*)(ws + k*ACT + 4);
            acc[0] = fmaf(x, w0.x, acc[0]);
            acc[1] = fmaf(x, w0.y, acc[1]);
            acc[2] = fmaf(x, w0.z, acc[2]);
            acc[3] = fmaf(x, w0.w, acc[3]);
            acc[4] = fmaf(x, w1v.x, acc[4]);
            acc[5] = fmaf(x, w1v.y, acc[5]);
            acc[6] = fmaf(x, w1v.z, acc[6]);
            acc[7] = fmaf(x, w1v.w, acc[7]);
        }
        float best = acc[0] + b3s[0];
        int bi = 0;
        #pragma unroll
        for (int c = 1; c < 8; c++) {
            float q = acc[c] + b3s[c];
            if (q > best) { best = q; bi = c; }   // first-max semantics
        }
        g_qs[(size_t)(b0 + r) * AGENTS + a]       = best;
        actions_out[(size_t)(b0 + r) * AGENTS + a] = (float)bi;
    }
}

// =============================================================================
// Kernel 2: skinny hypernet GEMMs: states @ {Whb, Whf, Wv1} (+bias, abs/relu).
// Grid BS/32 blocks, 256 threads, K-chunked in smem.
// =============================================================================
__global__ void __launch_bounds__(256) hyper_small_kernel(
    const float* __restrict__ S,
    const float* __restrict__ Whb, const float* __restrict__ bhb,
    const float* __restrict__ Whf, const float* __restrict__ bhf,
    const float* __restrict__ Wv1, const float* __restrict__ bv1)
{
    __shared__ __align__(16) float ss[64][36];   // transposed states chunk [k][row]
    __shared__ __align__(16) float wbs[64][32];
    __shared__ __align__(16) float wfs[64][32];
    __shared__ __align__(16) float wvs[64][32];

    const int b0  = blockIdx.x * 32;
    const int tid = threadIdx.x;
    const int e   = tid & 31;     // embedding col
    const int rg  = tid >> 5;     // row group (warp id), rows rg*4..rg*4+3

    float ab[4] = {0,0,0,0}, af[4] = {0,0,0,0}, av[4] = {0,0,0,0};

    for (int k0 = 0; k0 < SD; k0 += 64) {
        __syncthreads();
        for (int i = tid; i < 512; i += 256) {      // 32 rows x 16 float4
            int r = i >> 4, c4 = (i & 15) * 4;
            float4 v = *(const float4*)(S + (size_t)(b0 + r) * SD + k0 + c4);
            ss[c4+0][r] = v.x; ss[c4+1][r] = v.y; ss[c4+2][r] = v.z; ss[c4+3][r] = v.w;
        }
        for (int i = tid; i < 512; i += 256) {      // 64 k x 8 float4
            int kk = i >> 3, c = (i & 7) * 4;
            *(float4*)&wbs[kk][c] = *(const float4*)(Whb + (size_t)(k0+kk)*EMB + c);
            *(float4*)&wfs[kk][c] = *(const float4*)(Whf + (size_t)(k0+kk)*EMB + c);
            *(float4*)&wvs[kk][c] = *(const float4*)(Wv1 + (size_t)(k0+kk)*EMB + c);
        }
        __syncthreads();
        #pragma unroll 4
        for (int k = 0; k < 64; k++) {
            float wb = wbs[k][e], wf = wfs[k][e], wv = wvs[k][e];
            #pragma unroll
            for (int i = 0; i < 4; i++) {
                float s = ss[k][rg*4 + i];          // warp-broadcast
                ab[i] = fmaf(s, wb, ab[i]);
                af[i] = fmaf(s, wf, af[i]);
                av[i] = fmaf(s, wv, av[i]);
            }
        }
    }
    #pragma unroll
    for (int i = 0; i < 4; i++) {
        int b = b0 + rg*4 + i;
        g_sb[(size_t)b*EMB + e] = ab[i] + bhb[e];
        g_wf[(size_t)b*EMB + e] = fabsf(af[i] + bhf[e]);
        float r = av[i] + bv1[e];
        g_rv[(size_t)b*EMB + e] = r > 0.f ? r : 0.f;
    }
}

// =============================================================================
// Kernel 3: big GEMM C = states[4096,4096] @ Wh1[4096,4096]
// Epilogue: g_C[b][n] = qs[b][n/32] * |C + bh1[n]|
// 128x128 tile, BK=8, 8x8 per thread, 256 threads, grid (32,32).
// =============================================================================
__global__ void __launch_bounds__(256) hyper_gemm(
    const float* __restrict__ S,
    const float* __restrict__ Wh1,
    const float* __restrict__ bh1)
{
    __shared__ __align__(16) float As[8][132];   // transposed, padded
    __shared__ __align__(16) float Bs[8][128];

    const int bx = blockIdx.x;   // N tile
    const int by = blockIdx.y;   // M tile
    const int tid = threadIdx.x;

    const int a_row = tid >> 1;            // 0..127
    const int a_col = (tid & 1) * 4;       // 0 or 4
    const int b_row = tid >> 5;            // 0..7
    const int b_col = (tid & 31) * 4;

    const float* Ag = S   + (size_t)(by*128 + a_row) * SD + a_col;
    const float* Bg = Wh1 + (size_t)b_row * SD + bx*128 + b_col;

    const int tr = tid >> 4, tc = tid & 15;     // output 8x8 micro-tile

    float acc[8][8];
    #pragma unroll
    for (int i = 0; i < 8; i++)
        #pragma unroll
        for (int j = 0; j < 8; j++) acc[i][j] = 0.f;

    for (int k0 = 0; k0 < SD; k0 += 8) {
        float4 avec = *(const float4*)(Ag + k0);
        float4 bvec = *(const float4*)(Bg + (size_t)k0 * SD);
        __syncthreads();
        As[a_col+0][a_row] = avec.x;
        As[a_col+1][a_row] = avec.y;
        As[a_col+2][a_row] = avec.z;
        As[a_col+3][a_row] = avec.w;
        *(float4*)&Bs[b_row][b_col] = bvec;
        __syncthreads();

        #pragma unroll
        for (int k = 0; k < 8; k++) {
            float ar[8], br[8];
            *(float4*)(ar)   = *(const float4*)&As[k][tr*8];
            *(float4*)(ar+4) = *(const float4*)&As[k][tr*8 + 4];
            *(float4*)(br)   = *(const float4*)&Bs[k][tc*8];
            *(float4*)(br+4) = *(const float4*)&Bs[k][tc*8 + 4];
            #pragma unroll
            for (int i = 0; i < 8; i++)
                #pragma unroll
                for (int j = 0; j < 8; j++)
                    acc[i][j] = fmaf(ar[i], br[j], acc[i][j]);
        }
    }

    const int row0 = by*128 + tr*8;
    const int col0 = bx*128 + tc*8;
    float bia[8];
    #pragma unroll
    for (int j = 0; j < 8; j++) bia[j] = bh1[col0 + j];
    #pragma unroll
    for (int i = 0; i < 8; i++) {
        const int r = row0 + i;
        const float qv = g_qs[(size_t)r * AGENTS + (col0 >> 5)];  // col0%32 in {0,8,16,24} -> same agent for all 8 cols
        #pragma unroll
        for (int j = 0; j < 8; j++) {
            g_C[(size_t)r * SD + col0 + j] = qv * fabsf(acc[i][j] + bia[j]);
        }
    }
}

// =============================================================================
// Kernel 4: per-row mixing reduction -> q_tot.  Grid BS blocks, 128 threads.
// hidden_pre[e] = sum_a g_C[b][a*32+e];  hidden = elu(hp + sb);
// y = sum_e hidden*wf + sum_e rv*Wv2 + bv2
// =============================================================================
__global__ void __launch_bounds__(128) final_kernel(
    const float* __restrict__ Wv2, const float* __restrict__ bv2,
    float* __restrict__ qtot)
{
    __shared__ float red[128];
    const int b = blockIdx.x;
    const int t = threadIdx.x;
    const float* row = g_C + (size_t)b * SD;
    float p = 0.f;
    #pragma unroll 8
    for (int j = 0; j < SD/128; j++) p += row[t + 128*j];   // e = t % 32 stays fixed
    red[t] = p;
    __syncthreads();
    if (t < 32) {
        float hp = red[t] + red[t+32] + red[t+64] + red[t+96] + g_sb[(size_t)b*EMB + t];
        float hidden = hp > 0.f ? hp : expm1f(hp);
        float contrib = hidden * g_wf[(size_t)b*EMB + t] + g_rv[(size_t)b*EMB + t] * Wv2[t];
        #pragma unroll
        for (int o = 16; o > 0; o >>= 1)
            contrib += __shfl_down_sync(0xffffffffu, contrib, o);
        if (t == 0) qtot[b] = contrib + bv2[0];
    }
}

// =============================================================================
extern "C" void kernel_launch(void* const* d_in, const int* in_sizes, int n_in,
                              void* d_out, int out_size)
{
    const float* obs    = (const float*)d_in[0];
    const float* states = (const float*)d_in[1];
    const float* W1  = (const float*)d_in[2];
    const float* b1  = (const float*)d_in[3];
    const float* W2  = (const float*)d_in[4];
    const float* b2  = (const float*)d_in[5];
    const float* W3  = (const float*)d_in[6];
    const float* b3  = (const float*)d_in[7];
    const float* Wh1 = (const float*)d_in[8];
    const float* bh1 = (const float*)d_in[9];
    const float* Whb = (const float*)d_in[10];
    const float* bhb = (const float*)d_in[11];
    const float* Whf = (const float*)d_in[12];
    const float* bhf = (const float*)d_in[13];
    const float* Wv1 = (const float*)d_in[14];
    const float* bv1 = (const float*)d_in[15];
    const float* Wv2 = (const float*)d_in[16];
    const float* bv2 = (const float*)d_in[17];
    float* out = (float*)d_out;

    cudaFuncSetAttribute(mlp_kernel, cudaFuncAttributeMaxDynamicSharedMemorySize, MLP_SMEM);

    // output layout: [q_tot (BS floats) | actions as float (BS*AGENTS)]
    float* act_dst;
    if (out_size >= (int)(BS + BS*AGENTS)) {
        act_dst = out + BS;
    } else {
        void* p = 0;
        cudaGetSymbolAddress(&p, g_act_fallback);
        act_dst = (float*)p;
    }

    mlp_kernel<<<dim3(AGENTS, BS/MLP_BT), 256, MLP_SMEM>>>(
        obs, W1, b1, W2, b2, W3, b3, act_dst);
    hyper_small_kernel<<<BS/32, 256>>>(states, Whb, bhb, Whf, bhf, Wv1, bv1);
    hyper_gemm<<<dim3(32, 32), 256>>>(states, Wh1, bh1);
    final_kernel<<<BS, 128>>>(Wv2, bv2, out);
}

// round 6
// speedup vs baseline: 1.8114x; 1.8114x over previous
#include <cuda_runtime.h>
#include <cuda_bf16.h>
#include <stdint.h>
#include <math.h>

#define BS 4096
#define AGENTS 128
#define OBSD 128
#define ACT 8
#define SD 4096
#define EMB 32
#define H1 128
#define H2 64

// ---------------- scratch (static device globals; no allocation) ----------------
__device__ float g_qs[(size_t)BS * AGENTS];           // agent_qs [b][a]
__device__ float g_sb[(size_t)BS * EMB];              // states@Whb + bhb
__device__ float g_wf[(size_t)BS * EMB];              // |states@Whf + bhf|
__device__ float g_rv[(size_t)BS * EMB];              // relu(states@Wv1 + bv1)
__device__ float g_act_fallback[(size_t)BS * AGENTS];
__device__ float g_part[(size_t)64 * BS * EMB];       // partial sums [slab][b][e] 32MB

// bf16 split operands, plain row-major
__device__ __nv_bfloat16 g_Shi[(size_t)BS * SD];      // A hi  [m][k]
__device__ __nv_bfloat16 g_Slo[(size_t)BS * SD];      // A lo
__device__ __nv_bfloat16 g_Bhi[(size_t)SD * SD];      // B hi  [n][k]  (B[n][k] = Wh1[k][n])
__device__ __nv_bfloat16 g_Blo[(size_t)SD * SD];

// ============================ PTX helpers =====================================
__device__ __forceinline__ uint32_t smem_u32(const void* p) {
    uint32_t a;
    asm("{ .reg .u64 t; cvta.to.shared.u64 t, %1; cvt.u32.u64 %0, t; }" : "=r"(a) : "l"(p));
    return a;
}

__device__ __forceinline__ void cp16(uint32_t s, const void* g) {
    asm volatile("cp.async.cg.shared.global [%0], [%1], 16;" :: "r"(s), "l"(g));
}
#define CP_COMMIT() asm volatile("cp.async.commit_group;")
#define CP_WAIT1()  asm volatile("cp.async.wait_group 1;")
#define CP_WAIT0()  asm volatile("cp.async.wait_group 0;")

__device__ __forceinline__ void ldm4(uint32_t* r, uint32_t addr) {
    asm volatile("ldmatrix.sync.aligned.m8n8.x4.shared.b16 {%0,%1,%2,%3}, [%4];"
        : "=r"(r[0]), "=r"(r[1]), "=r"(r[2]), "=r"(r[3]) : "r"(addr));
}

__device__ __forceinline__ void mma_bf16(float* c, const uint32_t* a, const uint32_t* b) {
    asm volatile("mma.sync.aligned.m16n8k16.row.col.f32.bf16.bf16.f32 "
        "{%0,%1,%2,%3}, {%4,%5,%6,%7}, {%8,%9}, {%0,%1,%2,%3};"
        : "+f"(c[0]), "+f"(c[1]), "+f"(c[2]), "+f"(c[3])
        : "r"(a[0]), "r"(a[1]), "r"(a[2]), "r"(a[3]), "r"(b[0]), "r"(b[1]));
}

// =============================================================================
// Kernel 1: fused per-agent 3-layer MLP + max/argmax. 512 threads.
// =============================================================================
#define MLP_BT 64
#define MLP_SMEM ((64*132 + 64*68 + 64*132 + 128*128) * 4)

__global__ void __launch_bounds__(512) mlp_kernel(
    const float* __restrict__ obs,
    const float* __restrict__ W1, const float* __restrict__ b1,
    const float* __restrict__ W2, const float* __restrict__ b2,
    const float* __restrict__ W3, const float* __restrict__ b3,
    float* __restrict__ actions_out)
{
    extern __shared__ float sm[];
    float* x1s  = sm;                       // [64][132]
    float* x2s  = sm + 64*132;              // [64][68]
    float* obss = sm + 64*132 + 64*68;      // [64][132]
    float* ws   = sm + 64*132 + 64*68 + 64*132;  // up to [128][128]
    __shared__ float b1s[H1];
    __shared__ float b2s[H2];
    __shared__ float b3s[ACT];

    const int a   = blockIdx.x;
    const int b0  = blockIdx.y * MLP_BT;
    const int tid = threadIdx.x;

    if (tid < H1) b1s[tid] = b1[a*H1 + tid];
    if (tid < H2) b2s[tid] = b2[a*H2 + tid];
    if (tid < ACT) b3s[tid] = b3[a*ACT + tid];

    {
        const float4* w1g = (const float4*)(W1 + (size_t)a * OBSD * H1);
        float4* wd = (float4*)ws;
        for (int i = tid; i < OBSD*H1/4; i += 512) wd[i] = w1g[i];
    }
    for (int i = tid; i < MLP_BT * (OBSD/4); i += 512) {
        int r  = i >> 5;
        int c4 = i & 31;
        float4 v = ((const float4*)(obs + ((size_t)(b0 + r) * AGENTS + a) * OBSD))[c4];
        *(float4*)(obss + r*132 + c4*4) = v;
    }
    __syncthreads();

    // layer 1
    {
        const int ty = tid >> 5, tx = tid & 31;
        float acc[4][4];
        #pragma unroll
        for (int i = 0; i < 4; i++)
            #pragma unroll
            for (int j = 0; j < 4; j++) acc[i][j] = 0.f;

        #pragma unroll 4
        for (int k = 0; k < OBSD; k++) {
            float a0 = obss[(ty*4+0)*132 + k];
            float a1 = obss[(ty*4+1)*132 + k];
            float a2 = obss[(ty*4+2)*132 + k];
            float a3 = obss[(ty*4+3)*132 + k];
            float4 w = *(const float4*)(ws + k*H1 + tx*4);
            float wv[4] = {w.x, w.y, w.z, w.w};
            #pragma unroll
            for (int j = 0; j < 4; j++) {
                acc[0][j] = fmaf(a0, wv[j], acc[0][j]);
                acc[1][j] = fmaf(a1, wv[j], acc[1][j]);
                acc[2][j] = fmaf(a2, wv[j], acc[2][j]);
                acc[3][j] = fmaf(a3, wv[j], acc[3][j]);
            }
        }
        #pragma unroll
        for (int i = 0; i < 4; i++) {
            float4 o;
            float* ov = (float*)&o;
            #pragma unroll
            for (int j = 0; j < 4; j++) {
                float v = acc[i][j] + b1s[tx*4 + j];
                ov[j] = v > 0.f ? v : 0.f;
            }
            *(float4*)(x1s + (ty*4+i)*132 + tx*4) = o;
        }
    }
    __syncthreads();

    {
        const float4* w2g = (const float4*)(W2 + (size_t)a * H1 * H2);
        float4* wd = (float4*)ws;
        for (int i = tid; i < H1*H2/4; i += 512) wd[i] = w2g[i];
    }
    __syncthreads();

    // layer 2
    {
        const int ry = tid >> 4, tx = tid & 15;
        float acc[2][4];
        #pragma unroll
        for (int i = 0; i < 2; i++)
            #pragma unroll
            for (int j = 0; j < 4; j++) acc[i][j] = 0.f;

        #pragma unroll 4
        for (int k = 0; k < H1; k++) {
            float a0 = x1s[(ry*2+0)*132 + k];
            float a1 = x1s[(ry*2+1)*132 + k];
            float4 w = *(const float4*)(ws + k*H2 + tx*4);
            float wv[4] = {w.x, w.y, w.z, w.w};
            #pragma unroll
            for (int j = 0; j < 4; j++) {
                acc[0][j] = fmaf(a0, wv[j], acc[0][j]);
                acc[1][j] = fmaf(a1, wv[j], acc[1][j]);
            }
        }
        #pragma unroll
        for (int i = 0; i < 2; i++) {
            float4 o;
            float* ov = (float*)&o;
            #pragma unroll
            for (int j = 0; j < 4; j++) {
                float v = acc[i][j] + b2s[tx*4 + j];
                ov[j] = v > 0.f ? v : 0.f;
            }
            *(float4*)(x2s + (ry*2+i)*68 + tx*4) = o;
        }
    }
    __syncthreads();

    {
        const float4* w3g = (const float4*)(W3 + (size_t)a * H2 * ACT);
        float4* wd = (float4*)ws;
        for (int i = tid; i < H2*ACT/4; i += 512) wd[i] = w3g[i];
    }
    __syncthreads();

    // layer 3 + argmax
    if (tid < MLP_BT) {
        const int r = tid;
        float acc[8];
        #pragma unroll
        for (int c = 0; c < 8; c++) acc[c] = 0.f;
        #pragma unroll 4
        for (int k = 0; k < H2; k++) {
            float x = x2s[r*68 + k];
            float4 w0  = *(const float4*)(ws + k*ACT);
            float4 w1v = *(const float4*)(ws + k*ACT + 4);
            acc[0] = fmaf(x, w0.x, acc[0]);
            acc[1] = fmaf(x, w0.y, acc[1]);
            acc[2] = fmaf(x, w0.z, acc[2]);
            acc[3] = fmaf(x, w0.w, acc[3]);
            acc[4] = fmaf(x, w1v.x, acc[4]);
            acc[5] = fmaf(x, w1v.y, acc[5]);
            acc[6] = fmaf(x, w1v.z, acc[6]);
            acc[7] = fmaf(x, w1v.w, acc[7]);
        }
        float best = acc[0] + b3s[0];
        int bi = 0;
        #pragma unroll
        for (int c = 1; c < 8; c++) {
            float q = acc[c] + b3s[c];
            if (q > best) { best = q; bi = c; }
        }
        g_qs[(size_t)(b0 + r) * AGENTS + a]        = best;
        actions_out[(size_t)(b0 + r) * AGENTS + a] = (float)bi;
    }
}

// =============================================================================
// Conversion: states -> hi/lo bf16 row-major (elementwise, coalesced)
// =============================================================================
__global__ void __launch_bounds__(256) conv_S_kernel(const float* __restrict__ S)
{
    const size_t id = (size_t)blockIdx.x * 256 + threadIdx.x;   // one per 8 elems
    const float4* src = (const float4*)(S + id * 8);
    float4 v0 = src[0], v1 = src[1];
    float x[8] = {v0.x, v0.y, v0.z, v0.w, v1.x, v1.y, v1.z, v1.w};
    uint32_t hw[4], lw[4];
    #pragma unroll
    for (int p = 0; p < 4; p++) {
        __nv_bfloat16 h0 = __float2bfloat16(x[p*2]);
        __nv_bfloat16 h1 = __float2bfloat16(x[p*2+1]);
        __nv_bfloat16 l0 = __float2bfloat16(x[p*2]   - __bfloat162float(h0));
        __nv_bfloat16 l1 = __float2bfloat16(x[p*2+1] - __bfloat162float(h1));
        hw[p] = (uint32_t)__bfloat16_as_ushort(h0) | ((uint32_t)__bfloat16_as_ushort(h1) << 16);
        lw[p] = (uint32_t)__bfloat16_as_ushort(l0) | ((uint32_t)__bfloat16_as_ushort(l1) << 16);
    }
    ((uint4*)g_Shi)[id] = make_uint4(hw[0], hw[1], hw[2], hw[3]);
    ((uint4*)g_Slo)[id] = make_uint4(lw[0], lw[1], lw[2], lw[3]);
}

// =============================================================================
// Conversion + transpose: Wh1[k][n] -> B[n][k] hi/lo bf16 (64x64 smem tiles)
// =============================================================================
__global__ void __launch_bounds__(256) conv_W_kernel(const float* __restrict__ Wh1)
{
    __shared__ float tile[64][65];
    const int kt = blockIdx.x & 63;
    const int nt = blockIdx.x >> 6;
    const int tid = threadIdx.x;

    #pragma unroll
    for (int p = 0; p < 16; p++) {
        int idx = p * 256 + tid;
        int r = idx >> 6, c = idx & 63;      // r = k, c = n
        tile[r][c] = Wh1[(size_t)(kt*64 + r) * SD + nt*64 + c];
    }
    __syncthreads();

    #pragma unroll
    for (int p = 0; p < 2; p++) {
        int id = p * 256 + tid;
        int n = id >> 3, kc = id & 7;
        uint32_t hw[4], lw[4];
        #pragma unroll
        for (int q = 0; q < 4; q++) {
            float x0 = tile[kc*8 + q*2][n];
            float x1 = tile[kc*8 + q*2 + 1][n];
            __nv_bfloat16 h0 = __float2bfloat16(x0);
            __nv_bfloat16 h1 = __float2bfloat16(x1);
            __nv_bfloat16 l0 = __float2bfloat16(x0 - __bfloat162float(h0));
            __nv_bfloat16 l1 = __float2bfloat16(x1 - __bfloat162float(h1));
            hw[q] = (uint32_t)__bfloat16_as_ushort(h0) | ((uint32_t)__bfloat16_as_ushort(h1) << 16);
            lw[q] = (uint32_t)__bfloat16_as_ushort(l0) | ((uint32_t)__bfloat16_as_ushort(l1) << 16);
        }
        size_t off = ((size_t)(nt*64 + n) * SD + kt*64 + kc*8) / 8;
        ((uint4*)g_Bhi)[off] = make_uint4(hw[0], hw[1], hw[2], hw[3]);
        ((uint4*)g_Blo)[off] = make_uint4(lw[0], lw[1], lw[2], lw[3]);
    }
}

// =============================================================================
// mma.sync bf16 3-split GEMM. 128x128 CTA tile, BK=32, 3-stage cp.async.
// 8 warps: warpM = wid%4 (32 rows), warpN = wid/4 (64 cols).
// smem per operand per stage: [128 rows][4+1 pad float4] = 10240B (stride-5
// padding makes ldmatrix conflict-free: 5m mod 8 is a permutation).
// Epilogue folds qs*|acc+bh1| and writes agent-reduced partials to g_part.
// =============================================================================
#define GSTAGES 3
#define OP_BYTES 10240
#define STAGE_BYTES (4 * OP_BYTES)
#define GEMM_SMEM (GSTAGES * STAGE_BYTES)
#define NKT (SD / 32)

__global__ void __launch_bounds__(256) hyper_gemm_mma(const float* __restrict__ bh1)
{
    extern __shared__ char gsm[];
    __shared__ float sbias[128];

    const int tid = threadIdx.x;
    const int wid = tid >> 5, lane = tid & 31;
    const int warpM = wid & 3, warpN = wid >> 2;
    const int bx = blockIdx.x >> 5;    // N tile
    const int by = blockIdx.x & 31;    // M tile

    const uint32_t sbase = smem_u32(gsm);

    if (tid < 128) sbias[tid] = bh1[bx*128 + tid];

    // global base pointers (bytes)
    const char* Ahi_g = (const char*)(g_Shi + (size_t)(by*128) * SD);
    const char* Alo_g = (const char*)(g_Slo + (size_t)(by*128) * SD);
    const char* Bhi_g = (const char*)(g_Bhi + (size_t)(bx*128) * SD);
    const char* Blo_g = (const char*)(g_Blo + (size_t)(bx*128) * SD);

    // cp.async assignment: 512 16B-chunks per operand; thread handles ids {tid, tid+256}
    const int id0 = tid, id1 = tid + 256;
    const int m0 = id0 >> 2, c0 = id0 & 3;
    const int m1 = id1 >> 2, c1 = id1 & 3;
    const uint32_t s_off0 = (uint32_t)(m0*5 + c0) * 16;
    const uint32_t s_off1 = (uint32_t)(m1*5 + c1) * 16;

    #define ISSUE_STAGE(stg, kt_) do { \
        const uint32_t sb_ = sbase + (stg) * STAGE_BYTES; \
        const size_t g0_ = ((size_t)m0 * SD + (kt_)*32 + c0*8) * 2; \
        const size_t g1_ = ((size_t)m1 * SD + (kt_)*32 + c1*8) * 2; \
        cp16(sb_ + 0*OP_BYTES + s_off0, Ahi_g + g0_); \
        cp16(sb_ + 0*OP_BYTES + s_off1, Ahi_g + g1_); \
        cp16(sb_ + 1*OP_BYTES + s_off0, Alo_g + g0_); \
        cp16(sb_ + 1*OP_BYTES + s_off1, Alo_g + g1_); \
        cp16(sb_ + 2*OP_BYTES + s_off0, Bhi_g + g0_); \
        cp16(sb_ + 2*OP_BYTES + s_off1, Bhi_g + g1_); \
        cp16(sb_ + 3*OP_BYTES + s_off0, Blo_g + g0_); \
        cp16(sb_ + 3*OP_BYTES + s_off1, Blo_g + g1_); \
        CP_COMMIT(); \
    } while (0)

    // ldmatrix lane offsets (bytes within operand tile), per (tile, kstep)
    uint32_t offA[2][2], offB[4][2];
    {
        const int am = warpM*32 + (lane & 7) + ((lane >> 3) & 1) * 8;
        #pragma unroll
        for (int mt = 0; mt < 2; mt++)
            #pragma unroll
            for (int ks = 0; ks < 2; ks++)
                offA[mt][ks] = (uint32_t)((am + mt*16)*5 + ks*2 + (lane >> 4)) * 16;
        const int bn = warpN*64 + (lane & 7) + ((lane >> 4) & 1) * 8;
        #pragma unroll
        for (int ntp = 0; ntp < 4; ntp++)
            #pragma unroll
            for (int ks = 0; ks < 2; ks++)
                offB[ntp][ks] = (uint32_t)((bn + ntp*16)*5 + ks*2 + ((lane >> 3) & 1)) * 16;
    }

    float acc[2][8][4];
    #pragma unroll
    for (int mt = 0; mt < 2; mt++)
        #pragma unroll
        for (int nt = 0; nt < 8; nt++)
            #pragma unroll
            for (int q = 0; q < 4; q++) acc[mt][nt][q] = 0.f;

    // prologue: stages 0, 1
    ISSUE_STAGE(0, 0);
    ISSUE_STAGE(1, 1);

    for (int kt = 0; kt < NKT; kt++) {
        CP_WAIT1();
        __syncthreads();

        if (kt + 2 < NKT) ISSUE_STAGE((kt + 2) % GSTAGES, kt + 2);

        const uint32_t stg = sbase + (kt % GSTAGES) * STAGE_BYTES;
        const uint32_t aHi = stg + 0*OP_BYTES, aLo = stg + 1*OP_BYTES;
        const uint32_t bHi = stg + 2*OP_BYTES, bLo = stg + 3*OP_BYTES;

        #pragma unroll
        for (int ks = 0; ks < 2; ks++) {
            uint32_t ah[2][4], al[2][4], bh[8][2], bl[8][2];
            #pragma unroll
            for (int mt = 0; mt < 2; mt++) {
                ldm4(ah[mt], aHi + offA[mt][ks]);
                ldm4(al[mt], aLo + offA[mt][ks]);
            }
            #pragma unroll
            for (int ntp = 0; ntp < 4; ntp++) {
                uint32_t r[4];
                ldm4(r, bHi + offB[ntp][ks]);
                bh[2*ntp][0] = r[0]; bh[2*ntp][1] = r[1];
                bh[2*ntp+1][0] = r[2]; bh[2*ntp+1][1] = r[3];
                ldm4(r, bLo + offB[ntp][ks]);
                bl[2*ntp][0] = r[0]; bl[2*ntp][1] = r[1];
                bl[2*ntp+1][0] = r[2]; bl[2*ntp+1][1] = r[3];
            }
            #pragma unroll
            for (int mt = 0; mt < 2; mt++)
                #pragma unroll
                for (int nt = 0; nt < 8; nt++) {
                    mma_bf16(acc[mt][nt], ah[mt], bh[nt]);
                    mma_bf16(acc[mt][nt], al[mt], bh[nt]);
                    mma_bf16(acc[mt][nt], ah[mt], bl[nt]);
                }
        }
        __syncthreads();
    }

    // --------- epilogue: fold qs * |acc + bias|, reduce agents, store ---------
    const int slab = bx*2 + warpN;
    #pragma unroll
    for (int mt = 0; mt < 2; mt++) {
        #pragma unroll
        for (int rr = 0; rr < 2; rr++) {
            const int row = by*128 + warpM*32 + mt*16 + (lane >> 2) + rr*8;
            const float qv0 = g_qs[(size_t)row * AGENTS + bx*4 + warpN*2];
            const float qv1 = g_qs[(size_t)row * AGENTS + bx*4 + warpN*2 + 1];
            float part[8];
            #pragma unroll
            for (int s = 0; s < 8; s++) part[s] = 0.f;
            #pragma unroll
            for (int nt = 0; nt < 8; nt++) {
                const float qv = (nt < 4) ? qv0 : qv1;
                #pragma unroll
                for (int j = 0; j < 2; j++) {
                    const int col = warpN*64 + nt*8 + (lane & 3)*2 + j;
                    float v = acc[mt][nt][rr*2 + j] + sbias[col];
                    part[(nt & 3)*2 + j] = fmaf(qv, fabsf(v), part[(nt & 3)*2 + j]);
                }
            }
            float* dst = g_part + ((size_t)slab * BS + row) * EMB;
            #pragma unroll
            for (int k4 = 0; k4 < 4; k4++) {
                const int e = k4*8 + (lane & 3)*2;
                *(float2*)(dst + e) = make_float2(part[k4*2], part[k4*2 + 1]);
            }
        }
    }
}

// =============================================================================
// Kernel: skinny hypernet GEMMs
// =============================================================================
__global__ void __launch_bounds__(256) hyper_small_kernel(
    const float* __restrict__ S,
    const float* __restrict__ Whb, const float* __restrict__ bhb,
    const float* __restrict__ Whf, const float* __restrict__ bhf,
    const float* __restrict__ Wv1, const float* __restrict__ bv1)
{
    __shared__ __align__(16) float ss[64][36];
    __shared__ __align__(16) float wbs[64][32];
    __shared__ __align__(16) float wfs[64][32];
    __shared__ __align__(16) float wvs[64][32];

    const int b0  = blockIdx.x * 32;
    const int tid = threadIdx.x;
    const int e   = tid & 31;
    const int rg  = tid >> 5;

    float ab[4] = {0,0,0,0}, af[4] = {0,0,0,0}, av[4] = {0,0,0,0};

    for (int k0 = 0; k0 < SD; k0 += 64) {
        __syncthreads();
        for (int i = tid; i < 512; i += 256) {
            int r = i >> 4, c4 = (i & 15) * 4;
            float4 v = *(const float4*)(S + (size_t)(b0 + r) * SD + k0 + c4);
            ss[c4+0][r] = v.x; ss[c4+1][r] = v.y; ss[c4+2][r] = v.z; ss[c4+3][r] = v.w;
        }
        for (int i = tid; i < 512; i += 256) {
            int kk = i >> 3, c = (i & 7) * 4;
            *(float4*)&wbs[kk][c] = *(const float4*)(Whb + (size_t)(k0+kk)*EMB + c);
            *(float4*)&wfs[kk][c] = *(const float4*)(Whf + (size_t)(k0+kk)*EMB + c);
            *(float4*)&wvs[kk][c] = *(const float4*)(Wv1 + (size_t)(k0+kk)*EMB + c);
        }
        __syncthreads();
        #pragma unroll 4
        for (int k = 0; k < 64; k++) {
            float wb = wbs[k][e], wf = wfs[k][e], wv = wvs[k][e];
            #pragma unroll
            for (int i = 0; i < 4; i++) {
                float s = ss[k][rg*4 + i];
                ab[i] = fmaf(s, wb, ab[i]);
                af[i] = fmaf(s, wf, af[i]);
                av[i] = fmaf(s, wv, av[i]);
            }
        }
    }
    #pragma unroll
    for (int i = 0; i < 4; i++) {
        int b = b0 + rg*4 + i;
        g_sb[(size_t)b*EMB + e] = ab[i] + bhb[e];
        g_wf[(size_t)b*EMB + e] = fabsf(af[i] + bhf[e]);
        float r = av[i] + bv1[e];
        g_rv[(size_t)b*EMB + e] = r > 0.f ? r : 0.f;
    }
}

// =============================================================================
// Final mixing: sum partials over 64 slabs, elu, dot with w_final + V.
// =============================================================================
__global__ void __launch_bounds__(128) final_kernel(
    const float* __restrict__ Wv2, const float* __restrict__ bv2,
    float* __restrict__ qtot)
{
    const int b = blockIdx.x * 4 + (threadIdx.x >> 5);
    const int e = threadIdx.x & 31;
    float s = 0.f;
    #pragma unroll
    for (int sl = 0; sl < 64; sl++)
        s += g_part[((size_t)sl * BS + b) * EMB + e];
    float hp = s + g_sb[(size_t)b * EMB + e];
    float hidden = hp > 0.f ? hp : expm1f(hp);
    float contrib = hidden * g_wf[(size_t)b * EMB + e] + g_rv[(size_t)b * EMB + e] * Wv2[e];
    #pragma unroll
    for (int o = 16; o > 0; o >>= 1)
        contrib += __shfl_down_sync(0xffffffffu, contrib, o);
    if (e == 0) qtot[b] = contrib + bv2[0];
}

// =============================================================================
extern "C" void kernel_launch(void* const* d_in, const int* in_sizes, int n_in,
                              void* d_out, int out_size)
{
    const float* obs    = (const float*)d_in[0];
    const float* states = (const float*)d_in[1];
    const float* W1  = (const float*)d_in[2];
    const float* b1  = (const float*)d_in[3];
    const float* W2  = (const float*)d_in[4];
    const float* b2  = (const float*)d_in[5];
    const float* W3  = (const float*)d_in[6];
    const float* b3  = (const float*)d_in[7];
    const float* Wh1 = (const float*)d_in[8];
    const float* bh1 = (const float*)d_in[9];
    const float* Whb = (const float*)d_in[10];
    const float* bhb = (const float*)d_in[11];
    const float* Whf = (const float*)d_in[12];
    const float* bhf = (const float*)d_in[13];
    const float* Wv1 = (const float*)d_in[14];
    const float* bv1 = (const float*)d_in[15];
    const float* Wv2 = (const float*)d_in[16];
    const float* bv2 = (const float*)d_in[17];
    float* out = (float*)d_out;

    cudaFuncSetAttribute(mlp_kernel, cudaFuncAttributeMaxDynamicSharedMemorySize, MLP_SMEM);
    cudaFuncSetAttribute(hyper_gemm_mma, cudaFuncAttributeMaxDynamicSharedMemorySize, GEMM_SMEM);

    float* act_dst;
    if (out_size >= (int)(BS + BS*AGENTS)) {
        act_dst = out + BS;
    } else {
        void* p = 0;
        cudaGetSymbolAddress(&p, g_act_fallback);
        act_dst = (float*)p;
    }

    mlp_kernel<<<dim3(AGENTS, BS/MLP_BT), 512, MLP_SMEM>>>(
        obs, W1, b1, W2, b2, W3, b3, act_dst);
    conv_S_kernel<<<BS*SD/8/256, 256>>>(states);
    conv_W_kernel<<<4096, 256>>>(Wh1);
    hyper_small_kernel<<<BS/32, 256>>>(states, Whb, bhb, Whf, bhf, Wv1, bv1);
    hyper_gemm_mma<<<1024, 256, GEMM_SMEM>>>(bh1);
    final_kernel<<<BS/4, 128>>>(Wv2, bv2, out);
}

// round 7
// speedup vs baseline: 1.9682x; 1.0866x over previous
#include <cuda_runtime.h>
#include <cuda_bf16.h>
#include <stdint.h>
#include <math.h>

#define BS 4096
#define AGENTS 128
#define OBSD 128
#define ACT 8
#define SD 4096
#define EMB 32
#define H1 128
#define H2 64

// ---------------- scratch (static device globals; no allocation) ----------------
__device__ float g_qs[(size_t)BS * AGENTS];           // agent_qs [b][a]
__device__ float g_act_fallback[(size_t)BS * AGENTS];
__device__ float g_part[(size_t)64 * BS * EMB];       // GEMM partial sums [slab][b][e] 32MB
#define HKS 8
__device__ float g_hsp[(size_t)HKS * BS * 96];        // hyper_small partials [kz][b][96]

// bf16 split operands, plain row-major
__device__ __nv_bfloat16 g_Shi[(size_t)BS * SD];      // A hi  [m][k]
__device__ __nv_bfloat16 g_Slo[(size_t)BS * SD];      // A lo
__device__ __nv_bfloat16 g_Bhi[(size_t)SD * SD];      // B hi  [n][k]  (B[n][k] = Wh1[k][n])
__device__ __nv_bfloat16 g_Blo[(size_t)SD * SD];

// ============================ PTX helpers =====================================
__device__ __forceinline__ uint32_t smem_u32(const void* p) {
    uint32_t a;
    asm("{ .reg .u64 t; cvta.to.shared.u64 t, %1; cvt.u32.u64 %0, t; }" : "=r"(a) : "l"(p));
    return a;
}

__device__ __forceinline__ void cp16(uint32_t s, const void* g) {
    asm volatile("cp.async.cg.shared.global [%0], [%1], 16;" :: "r"(s), "l"(g));
}
#define CP_COMMIT() asm volatile("cp.async.commit_group;")
#define CP_WAIT2()  asm volatile("cp.async.wait_group 2;")

__device__ __forceinline__ void ldm4(uint32_t* r, uint32_t addr) {
    asm volatile("ldmatrix.sync.aligned.m8n8.x4.shared.b16 {%0,%1,%2,%3}, [%4];"
        : "=r"(r[0]), "=r"(r[1]), "=r"(r[2]), "=r"(r[3]) : "r"(addr));
}

__device__ __forceinline__ void mma_bf16(float* c, const uint32_t* a, const uint32_t* b) {
    asm volatile("mma.sync.aligned.m16n8k16.row.col.f32.bf16.bf16.f32 "
        "{%0,%1,%2,%3}, {%4,%5,%6,%7}, {%8,%9}, {%0,%1,%2,%3};"
        : "+f"(c[0]), "+f"(c[1]), "+f"(c[2]), "+f"(c[3])
        : "r"(a[0]), "r"(a[1]), "r"(a[2]), "r"(a[3]), "r"(b[0]), "r"(b[1]));
}

// =============================================================================
// Kernel 1: fused per-agent 3-layer MLP + max/argmax. 512 threads. (unchanged)
// =============================================================================
#define MLP_BT 64
#define MLP_SMEM ((64*132 + 64*68 + 64*132 + 128*128) * 4)

__global__ void __launch_bounds__(512) mlp_kernel(
    const float* __restrict__ obs,
    const float* __restrict__ W1, const float* __restrict__ b1,
    const float* __restrict__ W2, const float* __restrict__ b2,
    const float* __restrict__ W3, const float* __restrict__ b3,
    float* __restrict__ actions_out)
{
    extern __shared__ float sm[];
    float* x1s  = sm;                       // [64][132]
    float* x2s  = sm + 64*132;              // [64][68]
    float* obss = sm + 64*132 + 64*68;      // [64][132]
    float* ws   = sm + 64*132 + 64*68 + 64*132;  // up to [128][128]
    __shared__ float b1s[H1];
    __shared__ float b2s[H2];
    __shared__ float b3s[ACT];

    const int a   = blockIdx.x;
    const int b0  = blockIdx.y * MLP_BT;
    const int tid = threadIdx.x;

    if (tid < H1) b1s[tid] = b1[a*H1 + tid];
    if (tid < H2) b2s[tid] = b2[a*H2 + tid];
    if (tid < ACT) b3s[tid] = b3[a*ACT + tid];

    {
        const float4* w1g = (const float4*)(W1 + (size_t)a * OBSD * H1);
        float4* wd = (float4*)ws;
        for (int i = tid; i < OBSD*H1/4; i += 512) wd[i] = w1g[i];
    }
    for (int i = tid; i < MLP_BT * (OBSD/4); i += 512) {
        int r  = i >> 5;
        int c4 = i & 31;
        float4 v = ((const float4*)(obs + ((size_t)(b0 + r) * AGENTS + a) * OBSD))[c4];
        *(float4*)(obss + r*132 + c4*4) = v;
    }
    __syncthreads();

    // layer 1
    {
        const int ty = tid >> 5, tx = tid & 31;
        float acc[4][4];
        #pragma unroll
        for (int i = 0; i < 4; i++)
            #pragma unroll
            for (int j = 0; j < 4; j++) acc[i][j] = 0.f;

        #pragma unroll 4
        for (int k = 0; k < OBSD; k++) {
            float a0 = obss[(ty*4+0)*132 + k];
            float a1 = obss[(ty*4+1)*132 + k];
            float a2 = obss[(ty*4+2)*132 + k];
            float a3 = obss[(ty*4+3)*132 + k];
            float4 w = *(const float4*)(ws + k*H1 + tx*4);
            float wv[4] = {w.x, w.y, w.z, w.w};
            #pragma unroll
            for (int j = 0; j < 4; j++) {
                acc[0][j] = fmaf(a0, wv[j], acc[0][j]);
                acc[1][j] = fmaf(a1, wv[j], acc[1][j]);
                acc[2][j] = fmaf(a2, wv[j], acc[2][j]);
                acc[3][j] = fmaf(a3, wv[j], acc[3][j]);
            }
        }
        #pragma unroll
        for (int i = 0; i < 4; i++) {
            float4 o;
            float* ov = (float*)&o;
            #pragma unroll
            for (int j = 0; j < 4; j++) {
                float v = acc[i][j] + b1s[tx*4 + j];
                ov[j] = v > 0.f ? v : 0.f;
            }
            *(float4*)(x1s + (ty*4+i)*132 + tx*4) = o;
        }
    }
    __syncthreads();

    {
        const float4* w2g = (const float4*)(W2 + (size_t)a * H1 * H2);
        float4* wd = (float4*)ws;
        for (int i = tid; i < H1*H2/4; i += 512) wd[i] = w2g[i];
    }
    __syncthreads();

    // layer 2
    {
        const int ry = tid >> 4, tx = tid & 15;
        float acc[2][4];
        #pragma unroll
        for (int i = 0; i < 2; i++)
            #pragma unroll
            for (int j = 0; j < 4; j++) acc[i][j] = 0.f;

        #pragma unroll 4
        for (int k = 0; k < H1; k++) {
            float a0 = x1s[(ry*2+0)*132 + k];
            float a1 = x1s[(ry*2+1)*132 + k];
            float4 w = *(const float4*)(ws + k*H2 + tx*4);
            float wv[4] = {w.x, w.y, w.z, w.w};
            #pragma unroll
            for (int j = 0; j < 4; j++) {
                acc[0][j] = fmaf(a0, wv[j], acc[0][j]);
                acc[1][j] = fmaf(a1, wv[j], acc[1][j]);
            }
        }
        #pragma unroll
        for (int i = 0; i < 2; i++) {
            float4 o;
            float* ov = (float*)&o;
            #pragma unroll
            for (int j = 0; j < 4; j++) {
                float v = acc[i][j] + b2s[tx*4 + j];
                ov[j] = v > 0.f ? v : 0.f;
            }
            *(float4*)(x2s + (ry*2+i)*68 + tx*4) = o;
        }
    }
    __syncthreads();

    {
        const float4* w3g = (const float4*)(W3 + (size_t)a * H2 * ACT);
        float4* wd = (float4*)ws;
        for (int i = tid; i < H2*ACT/4; i += 512) wd[i] = w3g[i];
    }
    __syncthreads();

    // layer 3 + argmax
    if (tid < MLP_BT) {
        const int r = tid;
        float acc[8];
        #pragma unroll
        for (int c = 0; c < 8; c++) acc[c] = 0.f;
        #pragma unroll 4
        for (int k = 0; k < H2; k++) {
            float x = x2s[r*68 + k];
            float4 w0  = *(const float4*)(ws + k*ACT);
            float4 w1v = *(const float4*)(ws + k*ACT + 4);
            acc[0] = fmaf(x, w0.x, acc[0]);
            acc[1] = fmaf(x, w0.y, acc[1]);
            acc[2] = fmaf(x, w0.z, acc[2]);
            acc[3] = fmaf(x, w0.w, acc[3]);
            acc[4] = fmaf(x, w1v.x, acc[4]);
            acc[5] = fmaf(x, w1v.y, acc[5]);
            acc[6] = fmaf(x, w1v.z, acc[6]);
            acc[7] = fmaf(x, w1v.w, acc[7]);
        }
        float best = acc[0] + b3s[0];
        int bi = 0;
        #pragma unroll
        for (int c = 1; c < 8; c++) {
            float q = acc[c] + b3s[c];
            if (q > best) { best = q; bi = c; }
        }
        g_qs[(size_t)(b0 + r) * AGENTS + a]        = best;
        actions_out[(size_t)(b0 + r) * AGENTS + a] = (float)bi;
    }
}

// =============================================================================
// Conversion: states -> hi/lo bf16 row-major (elementwise, coalesced)
// =============================================================================
__global__ void __launch_bounds__(256) conv_S_kernel(const float* __restrict__ S)
{
    const size_t id = (size_t)blockIdx.x * 256 + threadIdx.x;   // one per 8 elems
    const float4* src = (const float4*)(S + id * 8);
    float4 v0 = src[0], v1 = src[1];
    float x[8] = {v0.x, v0.y, v0.z, v0.w, v1.x, v1.y, v1.z, v1.w};
    uint32_t hw[4], lw[4];
    #pragma unroll
    for (int p = 0; p < 4; p++) {
        __nv_bfloat16 h0 = __float2bfloat16(x[p*2]);
        __nv_bfloat16 h1 = __float2bfloat16(x[p*2+1]);
        __nv_bfloat16 l0 = __float2bfloat16(x[p*2]   - __bfloat162float(h0));
        __nv_bfloat16 l1 = __float2bfloat16(x[p*2+1] - __bfloat162float(h1));
        hw[p] = (uint32_t)__bfloat16_as_ushort(h0) | ((uint32_t)__bfloat16_as_ushort(h1) << 16);
        lw[p] = (uint32_t)__bfloat16_as_ushort(l0) | ((uint32_t)__bfloat16_as_ushort(l1) << 16);
    }
    ((uint4*)g_Shi)[id] = make_uint4(hw[0], hw[1], hw[2], hw[3]);
    ((uint4*)g_Slo)[id] = make_uint4(lw[0], lw[1], lw[2], lw[3]);
}

// =============================================================================
// Conversion + transpose: Wh1[k][n] -> B[n][k] hi/lo bf16 (64x64 smem tiles)
// =============================================================================
__global__ void __launch_bounds__(256) conv_W_kernel(const float* __restrict__ Wh1)
{
    __shared__ float tile[64][65];
    const int kt = blockIdx.x & 63;
    const int nt = blockIdx.x >> 6;
    const int tid = threadIdx.x;

    #pragma unroll
    for (int p = 0; p < 16; p++) {
        int idx = p * 256 + tid;
        int r = idx >> 6, c = idx & 63;      // r = k, c = n
        tile[r][c] = Wh1[(size_t)(kt*64 + r) * SD + nt*64 + c];
    }
    __syncthreads();

    #pragma unroll
    for (int p = 0; p < 2; p++) {
        int id = p * 256 + tid;
        int n = id >> 3, kc = id & 7;
        uint32_t hw[4], lw[4];
        #pragma unroll
        for (int q = 0; q < 4; q++) {
            float x0 = tile[kc*8 + q*2][n];
            float x1 = tile[kc*8 + q*2 + 1][n];
            __nv_bfloat16 h0 = __float2bfloat16(x0);
            __nv_bfloat16 h1 = __float2bfloat16(x1);
            __nv_bfloat16 l0 = __float2bfloat16(x0 - __bfloat162float(h0));
            __nv_bfloat16 l1 = __float2bfloat16(x1 - __bfloat162float(h1));
            hw[q] = (uint32_t)__bfloat16_as_ushort(h0) | ((uint32_t)__bfloat16_as_ushort(h1) << 16);
            lw[q] = (uint32_t)__bfloat16_as_ushort(l0) | ((uint32_t)__bfloat16_as_ushort(l1) << 16);
        }
        size_t off = ((size_t)(nt*64 + n) * SD + kt*64 + kc*8) / 8;
        ((uint4*)g_Bhi)[off] = make_uint4(hw[0], hw[1], hw[2], hw[3]);
        ((uint4*)g_Blo)[off] = make_uint4(lw[0], lw[1], lw[2], lw[3]);
    }
}

// =============================================================================
// mma.sync bf16 3-split GEMM. 128x128 CTA tile, BK=32, 4-stage cp.async,
// single __syncthreads per K-iter. 8 warps: warpM = wid%4, warpN = wid/4.
// Epilogue folds qs*|acc+bh1| and writes agent-reduced partials to g_part.
// =============================================================================
#define GSTAGES 4
#define OP_BYTES 10240
#define STAGE_BYTES (4 * OP_BYTES)
#define GEMM_SMEM (GSTAGES * STAGE_BYTES)
#define NKT (SD / 32)

__global__ void __launch_bounds__(256) hyper_gemm_mma(const float* __restrict__ bh1)
{
    extern __shared__ char gsm[];
    __shared__ float sbias[128];

    const int tid = threadIdx.x;
    const int wid = tid >> 5, lane = tid & 31;
    const int warpM = wid & 3, warpN = wid >> 2;
    const int bx = blockIdx.x >> 5;    // N tile
    const int by = blockIdx.x & 31;    // M tile

    const uint32_t sbase = smem_u32(gsm);

    if (tid < 128) sbias[tid] = bh1[bx*128 + tid];

    const char* Ahi_g = (const char*)(g_Shi + (size_t)(by*128) * SD);
    const char* Alo_g = (const char*)(g_Slo + (size_t)(by*128) * SD);
    const char* Bhi_g = (const char*)(g_Bhi + (size_t)(bx*128) * SD);
    const char* Blo_g = (const char*)(g_Blo + (size_t)(bx*128) * SD);

    const int id0 = tid, id1 = tid + 256;
    const int m0 = id0 >> 2, c0 = id0 & 3;
    const int m1 = id1 >> 2, c1 = id1 & 3;
    const uint32_t s_off0 = (uint32_t)(m0*5 + c0) * 16;
    const uint32_t s_off1 = (uint32_t)(m1*5 + c1) * 16;

    #define ISSUE_STAGE(stg, kt_) do { \
        const uint32_t sb_ = sbase + (stg) * STAGE_BYTES; \
        const size_t g0_ = ((size_t)m0 * SD + (size_t)(kt_)*32 + c0*8) * 2; \
        const size_t g1_ = ((size_t)m1 * SD + (size_t)(kt_)*32 + c1*8) * 2; \
        cp16(sb_ + 0*OP_BYTES + s_off0, Ahi_g + g0_); \
        cp16(sb_ + 0*OP_BYTES + s_off1, Ahi_g + g1_); \
        cp16(sb_ + 1*OP_BYTES + s_off0, Alo_g + g0_); \
        cp16(sb_ + 1*OP_BYTES + s_off1, Alo_g + g1_); \
        cp16(sb_ + 2*OP_BYTES + s_off0, Bhi_g + g0_); \
        cp16(sb_ + 2*OP_BYTES + s_off1, Bhi_g + g1_); \
        cp16(sb_ + 3*OP_BYTES + s_off0, Blo_g + g0_); \
        cp16(sb_ + 3*OP_BYTES + s_off1, Blo_g + g1_); \
        CP_COMMIT(); \
    } while (0)

    // ldmatrix lane offsets (bytes within operand tile), per (tile, kstep)
    uint32_t offA[2][2], offB[4][2];
    {
        const int am = warpM*32 + (lane & 7) + ((lane >> 3) & 1) * 8;
        #pragma unroll
        for (int mt = 0; mt < 2; mt++)
            #pragma unroll
            for (int ks = 0; ks < 2; ks++)
                offA[mt][ks] = (uint32_t)((am + mt*16)*5 + ks*2 + (lane >> 4)) * 16;
        const int bn = warpN*64 + (lane & 7) + ((lane >> 4) & 1) * 8;
        #pragma unroll
        for (int ntp = 0; ntp < 4; ntp++)
            #pragma unroll
            for (int ks = 0; ks < 2; ks++)
                offB[ntp][ks] = (uint32_t)((bn + ntp*16)*5 + ks*2 + ((lane >> 3) & 1)) * 16;
    }

    float acc[2][8][4];
    #pragma unroll
    for (int mt = 0; mt < 2; mt++)
        #pragma unroll
        for (int nt = 0; nt < 8; nt++)
            #pragma unroll
            for (int q = 0; q < 4; q++) acc[mt][nt][q] = 0.f;

    // prologue: stages 0..2
    ISSUE_STAGE(0, 0);
    ISSUE_STAGE(1, 1);
    ISSUE_STAGE(2, 2);

    for (int kt = 0; kt < NKT; kt++) {
        CP_WAIT2();
        __syncthreads();

        if (kt + 3 < NKT) ISSUE_STAGE((kt + 3) & 3, kt + 3);

        const uint32_t stg = sbase + (kt & 3) * STAGE_BYTES;
        const uint32_t aHi = stg + 0*OP_BYTES, aLo = stg + 1*OP_BYTES;
        const uint32_t bHi = stg + 2*OP_BYTES, bLo = stg + 3*OP_BYTES;

        #pragma unroll
        for (int ks = 0; ks < 2; ks++) {
            uint32_t ah[2][4], al[2][4], bh[8][2], bl[8][2];
            #pragma unroll
            for (int mt = 0; mt < 2; mt++) {
                ldm4(ah[mt], aHi + offA[mt][ks]);
                ldm4(al[mt], aLo + offA[mt][ks]);
            }
            #pragma unroll
            for (int ntp = 0; ntp < 4; ntp++) {
                uint32_t r[4];
                ldm4(r, bHi + offB[ntp][ks]);
                bh[2*ntp][0] = r[0]; bh[2*ntp][1] = r[1];
                bh[2*ntp+1][0] = r[2]; bh[2*ntp+1][1] = r[3];
                ldm4(r, bLo + offB[ntp][ks]);
                bl[2*ntp][0] = r[0]; bl[2*ntp][1] = r[1];
                bl[2*ntp+1][0] = r[2]; bl[2*ntp+1][1] = r[3];
            }
            #pragma unroll
            for (int mt = 0; mt < 2; mt++)
                #pragma unroll
                for (int nt = 0; nt < 8; nt++) {
                    mma_bf16(acc[mt][nt], ah[mt], bh[nt]);
                    mma_bf16(acc[mt][nt], al[mt], bh[nt]);
                    mma_bf16(acc[mt][nt], ah[mt], bl[nt]);
                }
        }
    }

    // --------- epilogue: fold qs * |acc + bias|, reduce agents, store ---------
    const int slab = bx*2 + warpN;
    #pragma unroll
    for (int mt = 0; mt < 2; mt++) {
        #pragma unroll
        for (int rr = 0; rr < 2; rr++) {
            const int row = by*128 + warpM*32 + mt*16 + (lane >> 2) + rr*8;
            const float qv0 = g_qs[(size_t)row * AGENTS + bx*4 + warpN*2];
            const float qv1 = g_qs[(size_t)row * AGENTS + bx*4 + warpN*2 + 1];
            float part[8];
            #pragma unroll
            for (int s = 0; s < 8; s++) part[s] = 0.f;
            #pragma unroll
            for (int nt = 0; nt < 8; nt++) {
                const float qv = (nt < 4) ? qv0 : qv1;
                #pragma unroll
                for (int j = 0; j < 2; j++) {
                    const int col = warpN*64 + nt*8 + (lane & 3)*2 + j;
                    float v = acc[mt][nt][rr*2 + j] + sbias[col];
                    part[(nt & 3)*2 + j] = fmaf(qv, fabsf(v), part[(nt & 3)*2 + j]);
                }
            }
            float* dst = g_part + ((size_t)slab * BS + row) * EMB;
            #pragma unroll
            for (int k4 = 0; k4 < 4; k4++) {
                const int e = k4*8 + (lane & 3)*2;
                *(float2*)(dst + e) = make_float2(part[k4*2], part[k4*2 + 1]);
            }
        }
    }
}

// =============================================================================
// Skinny hypernet GEMMs, K-split by HKS. Each block: 32 rows x K-slice of 512.
// Writes raw partials (no bias) to g_hsp[kz][b][96] = {Whb | Whf | Wv1} dots.
// =============================================================================
__global__ void __launch_bounds__(256) hyper_small_kernel(
    const float* __restrict__ S,
    const float* __restrict__ Whb,
    const float* __restrict__ Whf,
    const float* __restrict__ Wv1)
{
    __shared__ __align__(16) float ss[64][36];
    __shared__ __align__(16) float wbs[64][32];
    __shared__ __align__(16) float wfs[64][32];
    __shared__ __align__(16) float wvs[64][32];

    const int b0  = blockIdx.x * 32;
    const int kz  = blockIdx.y;
    const int kbeg = kz * (SD / HKS);
    const int tid = threadIdx.x;
    const int e   = tid & 31;
    const int rg  = tid >> 5;

    float ab[4] = {0,0,0,0}, af[4] = {0,0,0,0}, av[4] = {0,0,0,0};

    for (int kc = 0; kc < SD/HKS; kc += 64) {
        const int k0 = kbeg + kc;
        __syncthreads();
        for (int i = tid; i < 512; i += 256) {
            int r = i >> 4, c4 = (i & 15) * 4;
            float4 v = *(const float4*)(S + (size_t)(b0 + r) * SD + k0 + c4);
            ss[c4+0][r] = v.x; ss[c4+1][r] = v.y; ss[c4+2][r] = v.z; ss[c4+3][r] = v.w;
        }
        for (int i = tid; i < 512; i += 256) {
            int kk = i >> 3, c = (i & 7) * 4;
            *(float4*)&wbs[kk][c] = *(const float4*)(Whb + (size_t)(k0+kk)*EMB + c);
            *(float4*)&wfs[kk][c] = *(const float4*)(Whf + (size_t)(k0+kk)*EMB + c);
            *(float4*)&wvs[kk][c] = *(const float4*)(Wv1 + (size_t)(k0+kk)*EMB + c);
        }
        __syncthreads();
        #pragma unroll 4
        for (int k = 0; k < 64; k++) {
            float wb = wbs[k][e], wf = wfs[k][e], wv = wvs[k][e];
            #pragma unroll
            for (int i = 0; i < 4; i++) {
                float s = ss[k][rg*4 + i];
                ab[i] = fmaf(s, wb, ab[i]);
                af[i] = fmaf(s, wf, af[i]);
                av[i] = fmaf(s, wv, av[i]);
            }
        }
    }
    #pragma unroll
    for (int i = 0; i < 4; i++) {
        int b = b0 + rg*4 + i;
        float* dst = g_hsp + ((size_t)kz * BS + b) * 96;
        dst[e]      = ab[i];
        dst[32 + e] = af[i];
        dst[64 + e] = av[i];
    }
}

// =============================================================================
// Final mixing: reduce hyper_small K-slices (+bias/abs/relu), reduce GEMM
// slabs, elu, dot with w_final + V.
// =============================================================================
__global__ void __launch_bounds__(128) final_kernel(
    const float* __restrict__ bhb, const float* __restrict__ bhf,
    const float* __restrict__ bv1,
    const float* __restrict__ Wv2, const float* __restrict__ bv2,
    float* __restrict__ qtot)
{
    const int b = blockIdx.x * 4 + (threadIdx.x >> 5);
    const int e = threadIdx.x & 31;

    float sb = 0.f, wf = 0.f, rv = 0.f;
    #pragma unroll
    for (int kz = 0; kz < HKS; kz++) {
        const float* src = g_hsp + ((size_t)kz * BS + b) * 96;
        sb += src[e];
        wf += src[32 + e];
        rv += src[64 + e];
    }
    sb += bhb[e];
    wf = fabsf(wf + bhf[e]);
    rv += bv1[e];
    rv = rv > 0.f ? rv : 0.f;

    float s = 0.f;
    #pragma unroll
    for (int sl = 0; sl < 64; sl++)
        s += g_part[((size_t)sl * BS + b) * EMB + e];
    float hp = s + sb;
    float hidden = hp > 0.f ? hp : expm1f(hp);
    float contrib = hidden * wf + rv * Wv2[e];
    #pragma unroll
    for (int o = 16; o > 0; o >>= 1)
        contrib += __shfl_down_sync(0xffffffffu, contrib, o);
    if (e == 0) qtot[b] = contrib + bv2[0];
}

// =============================================================================
extern "C" void kernel_launch(void* const* d_in, const int* in_sizes, int n_in,
                              void* d_out, int out_size)
{
    const float* obs    = (const float*)d_in[0];
    const float* states = (const float*)d_in[1];
    const float* W1  = (const float*)d_in[2];
    const float* b1  = (const float*)d_in[3];
    const float* W2  = (const float*)d_in[4];
    const float* b2  = (const float*)d_in[5];
    const float* W3  = (const float*)d_in[6];
    const float* b3  = (const float*)d_in[7];
    const float* Wh1 = (const float*)d_in[8];
    const float* bh1 = (const float*)d_in[9];
    const float* Whb = (const float*)d_in[10];
    const float* bhb = (const float*)d_in[11];
    const float* Whf = (const float*)d_in[12];
    const float* bhf = (const float*)d_in[13];
    const float* Wv1 = (const float*)d_in[14];
    const float* bv1 = (const float*)d_in[15];
    const float* Wv2 = (const float*)d_in[16];
    const float* bv2 = (const float*)d_in[17];
    float* out = (float*)d_out;

    cudaFuncSetAttribute(mlp_kernel, cudaFuncAttributeMaxDynamicSharedMemorySize, MLP_SMEM);
    cudaFuncSetAttribute(hyper_gemm_mma, cudaFuncAttributeMaxDynamicSharedMemorySize, GEMM_SMEM);

    float* act_dst;
    if (out_size >= (int)(BS + BS*AGENTS)) {
        act_dst = out + BS;
    } else {
        void* p = 0;
        cudaGetSymbolAddress(&p, g_act_fallback);
        act_dst = (float*)p;
    }

    mlp_kernel<<<dim3(AGENTS, BS/MLP_BT), 512, MLP_SMEM>>>(
        obs, W1, b1, W2, b2, W3, b3, act_dst);
    conv_S_kernel<<<BS*SD/8/256, 256>>>(states);
    conv_W_kernel<<<4096, 256>>>(Wh1);
    hyper_small_kernel<<<dim3(BS/32, HKS), 256>>>(states, Whb, Whf, Wv1);
    hyper_gemm_mma<<<1024, 256, GEMM_SMEM>>>(bh1);
    final_kernel<<<BS/4, 128>>>(bhb, bhf, bv1, Wv2, bv2, out);
}